// round 14
// baseline (speedup 1.0000x reference)
#include <cuda_runtime.h>
#include <cstddef>

// ManyBodyVoxel: out[0, a, c=t*2+l, x, y, z] =
//   sum_n exp(coeff * || grid_l[x,y,z] - d[a,n]*mask_t[a,n] ||^2)
// R14: R13 consumer (thread = (y,z), 8 packed x-accumulators, warp-uniform X)
//      at R12 occupancy: grid = 1024 CTAs (a, l, xh, type-group) x 256 threads.
//      Group 0 -> types {H,C,N}, group 1 -> {O,S}; each CTA classifies and
//      tabulates only its own types. Exp rows by center-out recurrence.

#define NT 256

typedef unsigned long long u64;

__device__ __forceinline__ u64 pk2(float v) {
    u64 r; asm("mov.b64 %0, {%1, %2};" : "=l"(r) : "f"(v), "f"(v)); return r;
}
__device__ __forceinline__ u64 fma2(u64 a, u64 b, u64 c) {
    u64 d; asm("fma.rn.f32x2 %0, %1, %2, %3;" : "=l"(d) : "l"(a), "l"(b), "l"(c)); return d;
}
__device__ __forceinline__ u64 mul2(u64 a, u64 b) {
    u64 d; asm("mul.rn.f32x2 %0, %1, %2;" : "=l"(d) : "l"(a), "l"(b)); return d;
}
__device__ __forceinline__ void unpk(u64 v, float& lo, float& hi) {
    asm("mov.b64 {%0, %1}, %2;" : "=f"(lo), "=f"(hi) : "l"(v));
}

__global__ __launch_bounds__(NT, 8)
void mbv_kernel(const float* __restrict__ dist,   // (1,128,64,3) fp32
                const float* __restrict__ sigma,  // (1,) fp32
                const int*   __restrict__ anum,   // (128,64) int64 or int32 (auto-detect)
                float* __restrict__ out)          // (1,128,10,16,16,16) fp32
{
    const int b   = blockIdx.x;
    const int tg  = b & 1;            // type group: 0 -> {1,6,7}, 1 -> {8,16}
    const int xh  = (b >> 1) & 1;     // x half: [xh*8, xh*8+8)
    const int l   = (b >> 2) & 1;     // 0: L=8, 1: L=12
    const int a   = b >> 3;
    const int tid = threadIdx.x;
    const int zz  = tid & 15;
    const int yy  = tid >> 4;

    const int t0  = tg ? 3 : 0;       // first global type of this group
    const int nt  = tg ? 2 : 3;       // number of types in this group

    // Record (slot): 64 floats = 256B. x[16] @ +0, y[16] @ +64B, z[16] @ +128B.
    // Slots 0..ncls-1: this group's atoms (type-major compact); slot 40: base.
    __shared__ __align__(16) float tab[41 * 64];
    __shared__ float dsm[192];
    __shared__ short ord[64];
    __shared__ int   startc[3];
    __shared__ int   cntc[3];
    __shared__ int   nclss;

    const float s  = sigma[0];
    const float cf = -0.5f / (s * s);

    // ---- Phase 0: warp0 classifies (this group's types only); 32..223 stage dist ----
    if (tid < 32) {
        int4 p = ((const int4*)anum)[tid];            // probe row 0 (dtype)
        int4 q = ((const int4*)anum)[a * 32 + tid];   // int64 view
        int2 r = ((const int2*)anum)[a * 32 + tid];   // int32 view
        bool i32 = __any_sync(0xffffffffu, (p.y | p.w) != 0);
        int z0 = i32 ? r.x : q.x;
        int z1 = i32 ? r.y : q.z;
        unsigned lt = (1u << tid) - 1u;
        const int ZT[5] = {1, 6, 7, 8, 16};
        int base = 0;
        #pragma unroll
        for (int ti = 0; ti < 3; ti++) {
            if (ti < nt) {
                int zt = ZT[t0 + ti];
                unsigned m0 = __ballot_sync(0xffffffffu, z0 == zt);
                unsigned m1 = __ballot_sync(0xffffffffu, z1 == zt);
                int c0 = __popc(m0), c = c0 + __popc(m1);
                if (z0 == zt) ord[base + __popc(m0 & lt)]      = (short)(2 * tid);
                if (z1 == zt) ord[base + c0 + __popc(m1 & lt)] = (short)(2 * tid + 1);
                if (tid == 0) { startc[ti] = base; cntc[ti] = c; }
                base += c;
            }
        }
        if (tid == 0) nclss = base;
    } else if (tid < 224) {
        dsm[tid - 32] = dist[a * 192 + (tid - 32)];
    }

    __syncthreads();

    // ---- Phase 1: exp rows via center-out geometric recurrence ----
    {
        const float Lp   = l ? 12.0f : 8.0f;
        const float half = 0.5f * Lp;
        const float step = Lp * (1.0f / 15.0f);
        const float Brat = __expf(2.0f * cf * step * step);

        const int nrec = nclss + 1;
        if (tid < 3 * nrec) {                 // unit = (slot, axis), 16 ticks
            int slot = tid / 3;
            int ax   = tid - slot * 3;
            int isbase = (slot == nclss);
            int recid  = isbase ? 40 : slot;
            float dv   = isbase ? 0.0f : dsm[(int)ord[slot] * 3 + ax];
            float* dst = &tab[recid * 64 + ax * 16];

            float bse = -half - dv;
            int jc = __float2int_rn(-bse / step);   // tick nearest Gaussian peak
            jc = max(0, min(15, jc));
            float uc = bse + step * (float)jc;
            float fc = __expf(cf * uc * uc);
            float ru = __expf(cf * step * (2.0f * uc + step));
            float rd = __expf(cf * step * (step - 2.0f * uc));
            dst[jc] = fc;
            float f = fc, r = ru;
            for (int j = jc + 1; j < 16; j++) { f *= r; r *= Brat; dst[j] = f; }
            f = fc; r = rd;
            for (int j = jc - 1; j >= 0; j--) { f *= r; r *= Brat; dst[j] = f; }
        }
    }

    __syncthreads();

    // ---- Phase 2: consumer. Thread (yy,zz) accumulates x in [xh*8, xh*8+8) ----
    const char* tb = reinterpret_cast<const char*>(tab);
    const int offX = xh * 32;
    const int offy = 64 + yy * 4;
    const int offz = 128 + zz * 4;

    const char* br = tb + 40 * 256;    // base record
    const float byz = *(const float*)(br + offy) * *(const float*)(br + offz);
    const ulonglong2 BXa = *(const ulonglong2*)(br + offX);
    const ulonglong2 BXb = *(const ulonglong2*)(br + offX + 16);

    // out offset (floats): (a*10 + (t0+ti)*2 + l)*4096 + x*256 + y*16 + z
    float* op = out + (((size_t)(a * 10 + t0 * 2 + l)) << 12) + ((size_t)xh << 11)
                    + ((size_t)yy << 4) + (size_t)zz;

    for (int ti = 0; ti < nt; ti++) {
        const int c = cntc[ti];
        const u64 bw = pk2((float)(64 - c) * byz);
        u64 a0 = mul2(bw, BXa.x);
        u64 a1 = mul2(bw, BXa.y);
        u64 a2 = mul2(bw, BXb.x);
        u64 a3 = mul2(bw, BXb.y);

        const char* p = tb + startc[ti] * 256;
        for (int k = 0; k < c; k++) {
            float wy = *(const float*)(p + offy);
            float wz = *(const float*)(p + offz);
            ulonglong2 Xa = *(const ulonglong2*)(p + offX);        // uniform, 1 wf
            ulonglong2 Xb = *(const ulonglong2*)(p + offX + 16);   // uniform, 1 wf
            u64 w = pk2(wy * wz);
            a0 = fma2(w, Xa.x, a0);
            a1 = fma2(w, Xa.y, a1);
            a2 = fma2(w, Xb.x, a2);
            a3 = fma2(w, Xb.y, a3);
            p += 256;
        }

        float f0, f1, f2, f3, f4, f5, f6, f7;
        unpk(a0, f0, f1); unpk(a1, f2, f3);
        unpk(a2, f4, f5); unpk(a3, f6, f7);
        __stcs(op,        f0);
        __stcs(op +  256, f1);
        __stcs(op +  512, f2);
        __stcs(op +  768, f3);
        __stcs(op + 1024, f4);
        __stcs(op + 1280, f5);
        __stcs(op + 1536, f6);
        __stcs(op + 1792, f7);
        op += 2 * 4096;                // next type channel
    }
}

extern "C" void kernel_launch(void* const* d_in, const int* in_sizes, int n_in,
                              void* d_out, int out_size) {
    const float* dist = nullptr;
    const float* sig  = nullptr;
    const int*   an   = nullptr;
    for (int i = 0; i < n_in; i++) {
        if (in_sizes[i] == 1)          sig  = (const float*)d_in[i];
        else if (in_sizes[i] == 24576) dist = (const float*)d_in[i];
        else if (in_sizes[i] == 8192)  an   = (const int*)d_in[i];
    }
    if (!dist) dist = (const float*)d_in[0];
    if (!sig)  sig  = (const float*)d_in[1];
    if (!an)   an   = (const int*)d_in[2];

    mbv_kernel<<<1024, NT>>>(dist, sig, an, (float*)d_out);
}

// round 16
// speedup vs baseline: 1.2179x; 1.2179x over previous
#include <cuda_runtime.h>
#include <cstddef>

// ManyBodyVoxel: out[0, a, c=t*2+l, x, y, z] =
//   sum_n exp(coeff * || grid_l[x,y,z] - d[a,n]*mask_t[a,n] ||^2)
// R16: R15 with the static-assignment bug fixed: 4 lanes per atom
//      (n_my = 8w + lane>>2, ax = lane&3) covers all 64 atoms.
//      Single-barrier fused prologue, register-resident counts, R13 consumer.

#define NT 256

typedef unsigned long long u64;

__device__ __forceinline__ u64 pk2(float v) {
    u64 r; asm("mov.b64 %0, {%1, %2};" : "=l"(r) : "f"(v), "f"(v)); return r;
}
__device__ __forceinline__ u64 fma2(u64 a, u64 b, u64 c) {
    u64 d; asm("fma.rn.f32x2 %0, %1, %2, %3;" : "=l"(d) : "l"(a), "l"(b), "l"(c)); return d;
}
__device__ __forceinline__ u64 mul2(u64 a, u64 b) {
    u64 d; asm("mul.rn.f32x2 %0, %1, %2;" : "=l"(d) : "l"(a), "l"(b)); return d;
}
__device__ __forceinline__ void unpk(u64 v, float& lo, float& hi) {
    asm("mov.b64 {%0, %1}, %2;" : "=f"(lo), "=f"(hi) : "l"(v));
}

__global__ __launch_bounds__(NT)
void mbv_kernel(const float* __restrict__ dist,   // (1,128,64,3) fp32
                const float* __restrict__ sigma,  // (1,) fp32
                const int*   __restrict__ anum,   // (128,64) int64 or int32 (auto-detect)
                float* __restrict__ out)          // (1,128,10,16,16,16) fp32
{
    const int b    = blockIdx.x;
    const int xh   = b & 1;           // x half: [xh*8, xh*8+8)
    const int l    = (b >> 1) & 1;    // 0: L=8, 1: L=12
    const int a    = b >> 2;
    const int tid  = threadIdx.x;
    const int w    = tid >> 5;
    const int lane = tid & 31;
    const int zz   = tid & 15;
    const int yy   = tid >> 4;

    // Record (slot): 64 floats = 256B. x[16] @ +0, y[16] @ +64B, z[16] @ +128B.
    // Slots 0..ncls-1: classified atoms (type-major compact); slot 64: base (d=0).
    __shared__ __align__(16) float tab[65 * 64];

    const float s  = sigma[0];
    const float cf = -0.5f / (s * s);

    // ---- t=0 loads: statically-assigned atom/axis dist value + anum row ----
    const int n_my = 8 * w + (lane >> 2);   // 8 warps x 8 atoms = 64 atoms
    const int ax   = lane & 3;              // 0..2 = axis; 3 = base role (w0)
    float dv_my = 0.0f;
    if (ax < 3) dv_my = __ldg(&dist[(a * 64 + n_my) * 3 + ax]);

    int4 q = ((const int4*)anum)[a * 32 + lane];   // int64 view (2 atoms)
    int2 r = ((const int2*)anum)[a * 32 + lane];   // int32 view (2 atoms)
    bool i32 = __any_sync(0xffffffffu, (q.y | q.w) != 0);
    int z0 = i32 ? r.x : q.x;               // atom 2*lane
    int z1 = i32 ? r.y : q.z;               // atom 2*lane+1

    // ---- Per-warp redundant classification (counts stay in registers) ----
    unsigned lt = (1u << lane) - 1u;
    const int ZT[5] = {1, 6, 7, 8, 16};
    int startc[5], cntc[5];
    int code0 = 0, code1 = 0;               // slot | 0x100 if matched
    int base = 0;
    #pragma unroll
    for (int t = 0; t < 5; t++) {
        unsigned m0 = __ballot_sync(0xffffffffu, z0 == ZT[t]);
        unsigned m1 = __ballot_sync(0xffffffffu, z1 == ZT[t]);
        int c0 = __popc(m0), c = c0 + __popc(m1);
        if (z0 == ZT[t]) code0 = (base + __popc(m0 & lt)) | 0x100;
        if (z1 == ZT[t]) code1 = (base + c0 + __popc(m1 & lt)) | 0x100;
        startc[t] = base; cntc[t] = c;
        base += c;
    }

    // ---- Fetch my atom's slot from the lane that balloted it (intra-warp) ----
    int src = n_my >> 1;                    // in [0,31]
    int cA = __shfl_sync(0xffffffffu, code0, src);
    int cB = __shfl_sync(0xffffffffu, code1, src);
    int code = (n_my & 1) ? cB : cA;

    // ---- Write exp row (center-out geometric recurrence) ----
    {
        int recid = -1, wax = ax;
        float dv = dv_my;
        if (ax < 3) {
            if (code & 0x100) recid = code & 0xff;
        } else if (w == 0 && (lane >> 2) < 3) {   // lanes 3,7,11: base record axes 0..2
            recid = 64; wax = lane >> 2; dv = 0.0f;
        }
        if (recid >= 0) {
            const float Lp   = l ? 12.0f : 8.0f;
            const float half = 0.5f * Lp;
            const float step = Lp * (1.0f / 15.0f);
            const float Brat = __expf(2.0f * cf * step * step);
            float* dst = &tab[recid * 64 + wax * 16];

            float bse = -half - dv;
            int jc = __float2int_rn(-bse / step);   // tick nearest Gaussian peak
            jc = max(0, min(15, jc));
            float uc = bse + step * (float)jc;
            float fc = __expf(cf * uc * uc);
            float ru = __expf(cf * step * (2.0f * uc + step));
            float rd = __expf(cf * step * (step - 2.0f * uc));
            dst[jc] = fc;
            float f = fc, rr = ru;
            for (int j = jc + 1; j < 16; j++) { f *= rr; rr *= Brat; dst[j] = f; }
            f = fc; rr = rd;
            for (int j = jc - 1; j >= 0; j--) { f *= rr; rr *= Brat; dst[j] = f; }
        }
    }

    __syncthreads();   // the only barrier

    // ---- Consumer (R13): thread (yy,zz) accumulates x in [xh*8, xh*8+8) ----
    const char* tb = reinterpret_cast<const char*>(tab);
    const int offX = xh * 32;
    const int offy = 64 + yy * 4;
    const int offz = 128 + zz * 4;

    const char* br = tb + 64 * 256;    // base record
    const float byz = *(const float*)(br + offy) * *(const float*)(br + offz);
    const ulonglong2 BXa = *(const ulonglong2*)(br + offX);
    const ulonglong2 BXb = *(const ulonglong2*)(br + offX + 16);

    // out offset (floats): (a*10 + t*2 + l)*4096 + x*256 + y*16 + z, x = xh*8..
    float* op = out + (((size_t)(a * 10 + l)) << 12) + ((size_t)xh << 11)
                    + ((size_t)yy << 4) + (size_t)zz;

    #pragma unroll
    for (int t = 0; t < 5; t++) {
        const int c = cntc[t];
        const u64 bw = pk2((float)(64 - c) * byz);
        u64 a0 = mul2(bw, BXa.x);
        u64 a1 = mul2(bw, BXa.y);
        u64 a2 = mul2(bw, BXb.x);
        u64 a3 = mul2(bw, BXb.y);

        const char* p = tb + startc[t] * 256;
        for (int k = 0; k < c; k++) {
            float wy = *(const float*)(p + offy);
            float wz = *(const float*)(p + offz);
            ulonglong2 Xa = *(const ulonglong2*)(p + offX);        // uniform, 1 wf
            ulonglong2 Xb = *(const ulonglong2*)(p + offX + 16);   // uniform, 1 wf
            u64 ww = pk2(wy * wz);
            a0 = fma2(ww, Xa.x, a0);
            a1 = fma2(ww, Xa.y, a1);
            a2 = fma2(ww, Xb.x, a2);
            a3 = fma2(ww, Xb.y, a3);
            p += 256;
        }

        float f0, f1, f2, f3, f4, f5, f6, f7;
        unpk(a0, f0, f1); unpk(a1, f2, f3);
        unpk(a2, f4, f5); unpk(a3, f6, f7);
        __stcs(op,        f0);
        __stcs(op +  256, f1);
        __stcs(op +  512, f2);
        __stcs(op +  768, f3);
        __stcs(op + 1024, f4);
        __stcs(op + 1280, f5);
        __stcs(op + 1536, f6);
        __stcs(op + 1792, f7);
        op += 2 * 4096;                // next type channel
    }
}

extern "C" void kernel_launch(void* const* d_in, const int* in_sizes, int n_in,
                              void* d_out, int out_size) {
    const float* dist = nullptr;
    const float* sig  = nullptr;
    const int*   an   = nullptr;
    for (int i = 0; i < n_in; i++) {
        if (in_sizes[i] == 1)          sig  = (const float*)d_in[i];
        else if (in_sizes[i] == 24576) dist = (const float*)d_in[i];
        else if (in_sizes[i] == 8192)  an   = (const int*)d_in[i];
    }
    if (!dist) dist = (const float*)d_in[0];
    if (!sig)  sig  = (const float*)d_in[1];
    if (!an)   an   = (const int*)d_in[2];

    mbv_kernel<<<512, NT>>>(dist, sig, an, (float*)d_out);
}